// round 11
// baseline (speedup 1.0000x reference)
#include <cuda_runtime.h>
#include <cuda_bf16.h>

#define T_STEPS 256
#define BATCH   128
#define DIM_IN  512
#define HID     512
#define NQ      8
#define QDIM    256   // 2^8
#define CHUNKS  32    // 8 timesteps per chunk

// grid roles: [0,128) scanout ; [128,132) circuit ; [132, 132+2048) xdot
#define SCAN_BLKS 128
#define CIRC0     128
#define XDOT0     132
#define XDOT_BLKS 2048
#define GRID_BLKS (XDOT0 + XDOT_BLKS)

// ---------------- scratch (no allocations allowed) ----------------
__device__ float4 g_xdot[T_STEPS * BATCH];   // per (t,b): raw dots for f,i,g,o
// per gate: [0]=wsum  [1]=b0-phi  [2]=alpha/2  [3]=R/2  [4]=alpha  [5]=R
__device__ float  g_par[4][6];
// pipeline flags (zeroed by init_kernel each launch)
__device__ int    g_ccnt[CHUNKS];   // xdot blocks done per 8-t chunk (target 64)
__device__ int    g_parflag;        // circuits done (target 4)

__device__ __forceinline__ float2 cmul(float2 a, float2 b) {
    return make_float2(a.x * b.x - a.y * b.y, a.x * b.y + a.y * b.x);
}
__device__ __forceinline__ float2 cadd(float2 a, float2 b) {
    return make_float2(a.x + b.x, a.y + b.y);
}
__device__ __forceinline__ float htanh(float x) {
    float y;
    asm("tanh.approx.f32 %0, %1;" : "=f"(y) : "f"(x));
    return y;
}
__device__ __forceinline__ float dot4(float4 w, float4 x) {
    return w.x * x.x + w.y * x.y + w.z * x.z + w.w * x.w;
}
__device__ __forceinline__ int vload(const int* p) { return *(volatile const int*)p; }

// ---------------- init: zero the flags ----------------
__global__ void init_kernel()
{
    int i = threadIdx.x;
    if (i < CHUNKS) g_ccnt[i] = 0;
    if (i == 0) g_parflag = 0;
}

// ---------------- circuit: simulate one variational circuit ----------------
__device__ void circuit_block(int g, const float* __restrict__ P,
                              const float* __restrict__ W, const float* __restrict__ bv)
{
    __shared__ float2 a0[QDIM], a1[QDIM];
    __shared__ float  r0[QDIM], r1[QDIM], r2[QDIM];
    int d = threadIdx.x;

    a0[d] = make_float2(d == 0 ? 1.f : 0.f, 0.f);
    a1[d] = make_float2(d == QDIM / 2 ? 1.f : 0.f, 0.f);

    for (int l = 0; l < 2; l++) {
        for (int w = 0; w < NQ; w++) {
            const float* p = P + (l * NQ + w) * 3;
            float phi = p[0], th = p[1], om = p[2];
            float c, s;  __sincosf(0.5f * th, &s, &c);
            float cap, sap; __sincosf(0.5f * (phi + om), &sap, &cap);
            float cbm, sbm; __sincosf(0.5f * (phi - om), &sbm, &cbm);
            float2 m00 = make_float2(cap * c, -sap * c);     // ep*c
            float2 m01 = make_float2(-cbm * s, -sbm * s);    // -em*s
            float2 m10 = make_float2(cbm * s, -sbm * s);     // conj(em)*s
            float2 m11 = make_float2(cap * c, sap * c);      // conj(ep)*c

            int p7 = 7 - w;
            int mask = 1 << p7;
            int bit = (d >> p7) & 1;
            __syncthreads();
            float2 me0 = a0[d], pa0 = a0[d ^ mask];
            float2 me1 = a1[d], pa1 = a1[d ^ mask];
            __syncthreads();
            float2 n0, n1;
            if (!bit) {
                n0 = cadd(cmul(m00, me0), cmul(m01, pa0));
                n1 = cadd(cmul(m00, me1), cmul(m01, pa1));
            } else {
                n0 = cadd(cmul(m10, pa0), cmul(m11, me0));
                n1 = cadd(cmul(m10, pa1), cmul(m11, me1));
            }
            a0[d] = n0; a1[d] = n1;
        }
        for (int w = 0; w < NQ - 1; w++) {
            int pc = 7 - w, pt = 6 - w;
            __syncthreads();
            int src = ((d >> pc) & 1) ? (d ^ (1 << pt)) : d;
            float2 v0 = a0[src], v1 = a1[src];
            __syncthreads();
            a0[d] = v0; a1[d] = v1;
        }
    }
    __syncthreads();

    float z = (d < QDIM / 2) ? 1.f : -1.f;
    float2 c0 = a0[d], c1 = a1[d];
    r0[d] = z * (c0.x * c0.x + c0.y * c0.y);
    r1[d] = z * (c1.x * c1.x + c1.y * c1.y);
    r2[d] = z * (c0.y * c1.x - c0.x * c1.y);
    __syncthreads();
    for (int off = QDIM / 2; off; off >>= 1) {
        if (d < off) { r0[d] += r0[d + off]; r1[d] += r1[d + off]; r2[d] += r2[d + off]; }
        __syncthreads();
    }
    float S00 = r0[0], S11 = r1[0], S01 = r2[0];
    __syncthreads();

    r0[d] = W[512 + d] + W[512 + QDIM + d];
    __syncthreads();
    for (int off = QDIM / 2; off; off >>= 1) {
        if (d < off) r0[d] += r0[d + off];
        __syncthreads();
    }
    if (d == 0) {
        float alpha = 0.5f * (S00 + S11);
        float beta  = 0.5f * (S00 - S11);
        float gamma = -S01;
        float R   = sqrtf(beta * beta + gamma * gamma);
        float phi = atan2f(gamma, beta);
        g_par[g][0] = r0[0];          // wsum
        g_par[g][1] = bv[0] - phi;    // theta offset
        g_par[g][2] = 0.5f * alpha;
        g_par[g][3] = 0.5f * R;
        g_par[g][4] = alpha;
        g_par[g][5] = R;
        __threadfence();              // release g_par
        atomicAdd(&g_parflag, 1);
    }
}

__device__ __forceinline__ float ptanh_half(float x) {   // |x| <= ~0.55
    float t = x * x;
    float p = fmaf(t, -17.f / 315.f, 2.f / 15.f);
    p = fmaf(t, p, -1.f / 3.f);
    p = fmaf(t, p, 1.f);
    return x * p;
}

// ---------------- fused kernel ----------------
__global__ void __launch_bounds__(256, 4) pipe_kernel(
    float4* __restrict__ out,
    const float* __restrict__ X,
    const float* __restrict__ Wf, const float* __restrict__ Wi,
    const float* __restrict__ Wg, const float* __restrict__ Wo,
    const float* __restrict__ bfv, const float* __restrict__ biv,
    const float* __restrict__ bgv, const float* __restrict__ bov,
    const float* __restrict__ Pf, const float* __restrict__ Pi,
    const float* __restrict__ Pg, const float* __restrict__ Po)
{
    int bid = blockIdx.x;
    int tid = threadIdx.x;

    // ============ role: circuit ============
    if (bid >= CIRC0 && bid < XDOT0) {
        int g = bid - CIRC0;
        const float* P  = (g == 0) ? Pf : (g == 1) ? Pi : (g == 2) ? Pg : Po;
        const float* W  = (g == 0) ? Wf : (g == 1) ? Wi : (g == 2) ? Wg : Wo;
        const float* bv = (g == 0) ? bfv : (g == 1) ? biv : (g == 2) ? bgv : bov;
        circuit_block(g, P, W, bv);
        return;
    }

    // ============ role: xdot producer (R8-proven form) ============
    if (bid >= XDOT0) {
        int j    = bid - XDOT0;              // 0..2047 ; 16 rows per block
        int warp = tid >> 5;
        int lane = tid & 31;
        int rA   = j * 16 + warp * 2;        // rows rA, rA+1

        const float4* xa = (const float4*)(X + (size_t)rA * DIM_IN);
        const float4* xb = xa + (DIM_IN / 4);

        float4 A0 = xa[lane], A1 = xa[lane + 32], A2 = xa[lane + 64], A3 = xa[lane + 96];
        float4 B0 = xb[lane], B1 = xb[lane + 32], B2 = xb[lane + 64], B3 = xb[lane + 96];

        float fA, fB, iA, iB, gA, gB, oA, oB;

#define GDOT(Wp, dA, dB)                                                          \
    {                                                                             \
        const float4* w4 = (const float4*)(Wp);                                   \
        float4 w0 = __ldg(w4 + lane),      w1 = __ldg(w4 + lane + 32),            \
               w2 = __ldg(w4 + lane + 64), w3 = __ldg(w4 + lane + 96);            \
        dA = dot4(w0, A0) + dot4(w1, A1) + dot4(w2, A2) + dot4(w3, A3);           \
        dB = dot4(w0, B0) + dot4(w1, B1) + dot4(w2, B2) + dot4(w3, B3);           \
    }
        GDOT(Wf, fA, fB)
        GDOT(Wi, iA, iB)
        GDOT(Wg, gA, gB)
        GDOT(Wo, oA, oB)
#undef GDOT

#pragma unroll
        for (int o = 16; o; o >>= 1) {
            fA += __shfl_xor_sync(0xffffffffu, fA, o);
            fB += __shfl_xor_sync(0xffffffffu, fB, o);
            iA += __shfl_xor_sync(0xffffffffu, iA, o);
            iB += __shfl_xor_sync(0xffffffffu, iB, o);
            gA += __shfl_xor_sync(0xffffffffu, gA, o);
            gB += __shfl_xor_sync(0xffffffffu, gB, o);
            oA += __shfl_xor_sync(0xffffffffu, oA, o);
            oB += __shfl_xor_sync(0xffffffffu, oB, o);
        }
        if (lane == 0) {
            g_xdot[rA]     = make_float4(fA, iA, gA, oA);
            g_xdot[rA + 1] = make_float4(fB, iB, gB, oB);
        }
        __syncthreads();
        if (tid == 0) {
            __threadfence();                     // release this block's 16 rows
            atomicAdd(&g_ccnt[j >> 6], 1);       // chunk complete at 64
        }
        return;
    }

    // ============ role: scanout (one block per batch element) ============
    {
        int b    = bid;
        int warp = tid >> 5;
        int lane = tid & 31;

        __shared__ float sH[4][8];      // 4-deep chunk ring
        __shared__ float sHx, sCx;      // final h, c
        __shared__ int   s_wprog;       // chunks published by compute (33 = final)
        __shared__ int   s_wdone[8];    // per-writer-warp chunks written

        if (tid == 0) s_wprog = 0;
        if (tid < 8)  s_wdone[tid] = 0;
        __syncthreads();

        if (warp == 0) {
            if (lane == 0) {
                // wait for circuit parameters
                while (vload(&g_parflag) < 4) __nanosleep(64);
                __threadfence();

                float ws_f = __ldcg(&g_par[0][0]), A2_f = __ldcg(&g_par[0][2]), R2_f = __ldcg(&g_par[0][3]);
                float ws_i = __ldcg(&g_par[1][0]), A2_i = __ldcg(&g_par[1][2]), R2_i = __ldcg(&g_par[1][3]);
                float ws_g = __ldcg(&g_par[2][0]), A_g  = __ldcg(&g_par[2][4]), R_g  = __ldcg(&g_par[2][5]);
                float ws_o = __ldcg(&g_par[3][0]), A2_o = __ldcg(&g_par[3][2]), R2_o = __ldcg(&g_par[3][3]);
                float off_f = __ldcg(&g_par[0][1]), off_i = __ldcg(&g_par[1][1]);
                float off_g = __ldcg(&g_par[2][1]), off_o = __ldcg(&g_par[3][1]);

                float H = 0.f, C = 0.f;
                const float4* Xd = g_xdot;

#define LOADADJ(t) \
    ({ float4 v_ = __ldcg(&Xd[(t) * BATCH + b]); \
       v_.x += off_f; v_.y += off_i; v_.z += off_g; v_.w += off_o; v_; })

                // wait for chunk 0 inputs, preload ring
                while (vload(&g_ccnt[0]) < 64) __nanosleep(64);
                __threadfence();
                float4 q[8];
#pragma unroll
                for (int j = 0; j < 8; j++) q[j] = LOADADJ(j);

#define STEP(xd, kk, jj)                                              \
    {                                                                 \
        float cf = __cosf(fmaf(H, ws_f, (xd).x));                     \
        float ci = __cosf(fmaf(H, ws_i, (xd).y));                     \
        float cg = __cosf(fmaf(H, ws_g, (xd).z));                     \
        float co = __cosf(fmaf(H, ws_o, (xd).w));                     \
        float fv = fmaf(ptanh_half(fmaf(R2_f, cf, A2_f)), 0.5f, 0.5f);\
        float iv = fmaf(ptanh_half(fmaf(R2_i, ci, A2_i)), 0.5f, 0.5f);\
        float gv = htanh(fmaf(R_g, cg, A_g));                         \
        float ov = fmaf(ptanh_half(fmaf(R2_o, co, A2_o)), 0.5f, 0.5f);\
        C = fmaf(fv, C, iv * gv);                                     \
        H = ov * htanh(C);                                            \
        sH[(kk) & 3][jj] = H;                                         \
    }

#pragma unroll 1
                for (int k = 0; k < CHUNKS; k++) {
                    // inputs for NEXT chunk (prefetched inside this chunk)
                    if (k + 1 < CHUNKS) {
                        while (vload(&g_ccnt[k + 1]) < 64) __nanosleep(64);
                        __threadfence();
                    }
                    // ring backpressure: slot (k&3) must be drained by all writers
                    if (k >= 4) {
                        for (int w = 1; w < 8; w++)
                            while (vload(&s_wdone[w]) < k - 3) __nanosleep(32);
                    }
#pragma unroll
                    for (int j = 0; j < 8; j++) {
                        float4 cur = q[j];
                        if (k + 1 < CHUNKS) q[j] = LOADADJ((k + 1) * 8 + j);
                        STEP(cur, k, j);
                    }
                    __threadfence_block();                   // release sH slot
                    *(volatile int*)&s_wprog = k + 1;
                }
                sHx = sH[(CHUNKS - 1) & 3][7];
                sCx = C;
                __threadfence_block();
                *(volatile int*)&s_wprog = CHUNKS + 1;       // final sentinel
#undef STEP
#undef LOADADJ
            }
        } else {
            // -------- writer warps 1..7 --------
            const unsigned OUT4 = (unsigned)T_STEPS * BATCH * (HID / 4); // 4,194,304
            const unsigned HB4  = (unsigned)BATCH * (HID / 4);           // 16,384
            int wtid = tid - 32;                  // 0..223

#pragma unroll 1
            for (int c = 0; c < CHUNKS; c++) {
                while (*(volatile int*)&s_wprog < c + 1) __nanosleep(64);
                __threadfence_block();
                const float* hs = sH[c & 3];
                unsigned rowbase = (unsigned)c * 8u;
#pragma unroll 1
                for (int u = wtid; u < 1024; u += 224) {
                    int tl  = u >> 7;             // 0..7
                    int pos = u & 127;            // float4 within 512-wide row
                    float v = hs[tl];
                    unsigned idx = ((rowbase + tl) * BATCH + (unsigned)b) * (HID / 4) + pos;
                    __stcs(out + idx, make_float4(v, v, v, v));
                }
                if (lane == 0) *(volatile int*)&s_wdone[warp] = c + 1;
            }
            // tail: hx, cx
            while (*(volatile int*)&s_wprog < CHUNKS + 1) __nanosleep(64);
            __threadfence_block();
            float hfin = sHx, cfin = sCx;
#pragma unroll 1
            for (int u = wtid; u < 256; u += 224) {
                unsigned idx = (u < 128)
                    ? OUT4 + (unsigned)b * (HID / 4) + u
                    : OUT4 + HB4 + (unsigned)b * (HID / 4) + (u - 128);
                float v = (u < 128) ? hfin : cfin;
                __stcs(out + idx, make_float4(v, v, v, v));
            }
        }
    }
}

// ---------------- launch ----------------
extern "C" void kernel_launch(void* const* d_in, const int* in_sizes, int n_in,
                              void* d_out, int out_size)
{
    const float* X  = (const float*)d_in[0];
    const float* Wf = (const float*)d_in[1];
    const float* bf = (const float*)d_in[2];
    const float* Pf = (const float*)d_in[3];
    const float* Wi = (const float*)d_in[4];
    const float* bi = (const float*)d_in[5];
    const float* Pi = (const float*)d_in[6];
    const float* Wg = (const float*)d_in[7];
    const float* bg = (const float*)d_in[8];
    const float* Pg = (const float*)d_in[9];
    const float* Wo = (const float*)d_in[10];
    const float* bo = (const float*)d_in[11];
    const float* Po = (const float*)d_in[12];

    init_kernel<<<1, 64>>>();

    pipe_kernel<<<GRID_BLKS, 256>>>(
        (float4*)d_out, X,
        Wf, Wi, Wg, Wo,
        bf, bi, bg, bo,
        Pf, Pi, Pg, Po);
}

// round 14
// speedup vs baseline: 1.2688x; 1.2688x over previous
#include <cuda_runtime.h>
#include <cuda_bf16.h>

#define T_STEPS 256
#define BATCH   128
#define DIM_IN  512
#define HID     512
#define NQ      8
#define QDIM    256   // 2^8
#define CHUNKS  32    // 8 timesteps per chunk

typedef unsigned long long ull;

// ---------------- scratch (no allocations allowed) ----------------
__device__ float4 g_xdot[T_STEPS * BATCH];   // per (t,b): raw dots for f,i,g,o
// per gate: [0]=wsum  [1]=b0-phi  [2]=alpha/2  [3]=R/2  [4]=alpha  [5]=R
__device__ float  g_par[4][6];

__device__ __forceinline__ float2 cmul(float2 a, float2 b) {
    return make_float2(a.x * b.x - a.y * b.y, a.x * b.y + a.y * b.x);
}
__device__ __forceinline__ float2 cadd(float2 a, float2 b) {
    return make_float2(a.x + b.x, a.y + b.y);
}
__device__ __forceinline__ float htanh(float x) {
    float y;
    asm("tanh.approx.f32 %0, %1;" : "=f"(y) : "f"(x));
    return y;
}
__device__ __forceinline__ float dot4(float4 w, float4 x) {
    return w.x * x.x + w.y * x.y + w.z * x.z + w.w * x.w;
}

// ---------------- packed f32x2 helpers ----------------
__device__ __forceinline__ ull pk(float a, float b) {
    ull r; asm("mov.b64 %0, {%1, %2};" : "=l"(r) : "f"(a), "f"(b)); return r;
}
__device__ __forceinline__ float2 upk(ull v) {
    float2 r; asm("mov.b64 {%0, %1}, %2;" : "=f"(r.x), "=f"(r.y) : "l"(v)); return r;
}
__device__ __forceinline__ ull bc2(float v) { return pk(v, v); }
__device__ __forceinline__ ull fma2(ull a, ull b, ull c) {
    ull d; asm("fma.rn.f32x2 %0, %1, %2, %3;" : "=l"(d) : "l"(a), "l"(b), "l"(c)); return d;
}
__device__ __forceinline__ ull mul2(ull a, ull b) {
    ull d; asm("mul.rn.f32x2 %0, %1, %2;" : "=l"(d) : "l"(a), "l"(b)); return d;
}
__device__ __forceinline__ ull add2(ull a, ull b) {
    ull d; asm("add.rn.f32x2 %0, %1, %2;" : "=l"(d) : "l"(a), "l"(b)); return d;
}
__device__ __forceinline__ ull cos2p(ull v) {
    float2 t = upk(v); return pk(__cosf(t.x), __cosf(t.y));
}
__device__ __forceinline__ ull tanh2p(ull v) {
    float2 t = upk(v); return pk(htanh(t.x), htanh(t.y));
}

// ---------------- circuit: simulate one variational circuit ----------------
__device__ void circuit_block(int g, const float* __restrict__ P,
                              const float* __restrict__ W, const float* __restrict__ bv)
{
    __shared__ float2 a0[QDIM], a1[QDIM];
    __shared__ float  r0[QDIM], r1[QDIM], r2[QDIM];
    int d = threadIdx.x;

    a0[d] = make_float2(d == 0 ? 1.f : 0.f, 0.f);
    a1[d] = make_float2(d == QDIM / 2 ? 1.f : 0.f, 0.f);

    for (int l = 0; l < 2; l++) {
        for (int w = 0; w < NQ; w++) {
            const float* p = P + (l * NQ + w) * 3;
            float phi = p[0], th = p[1], om = p[2];
            float c, s;  __sincosf(0.5f * th, &s, &c);
            float cap, sap; __sincosf(0.5f * (phi + om), &sap, &cap);
            float cbm, sbm; __sincosf(0.5f * (phi - om), &sbm, &cbm);
            float2 m00 = make_float2(cap * c, -sap * c);     // ep*c
            float2 m01 = make_float2(-cbm * s, -sbm * s);    // -em*s
            float2 m10 = make_float2(cbm * s, -sbm * s);     // conj(em)*s
            float2 m11 = make_float2(cap * c, sap * c);      // conj(ep)*c

            int p7 = 7 - w;
            int mask = 1 << p7;
            int bit = (d >> p7) & 1;
            __syncthreads();
            float2 me0 = a0[d], pa0 = a0[d ^ mask];
            float2 me1 = a1[d], pa1 = a1[d ^ mask];
            __syncthreads();
            float2 n0, n1;
            if (!bit) {
                n0 = cadd(cmul(m00, me0), cmul(m01, pa0));
                n1 = cadd(cmul(m00, me1), cmul(m01, pa1));
            } else {
                n0 = cadd(cmul(m10, pa0), cmul(m11, me0));
                n1 = cadd(cmul(m10, pa1), cmul(m11, me1));
            }
            a0[d] = n0; a1[d] = n1;
        }
        for (int w = 0; w < NQ - 1; w++) {
            int pc = 7 - w, pt = 6 - w;
            __syncthreads();
            int src = ((d >> pc) & 1) ? (d ^ (1 << pt)) : d;
            float2 v0 = a0[src], v1 = a1[src];
            __syncthreads();
            a0[d] = v0; a1[d] = v1;
        }
    }
    __syncthreads();

    float z = (d < QDIM / 2) ? 1.f : -1.f;
    float2 c0 = a0[d], c1 = a1[d];
    r0[d] = z * (c0.x * c0.x + c0.y * c0.y);
    r1[d] = z * (c1.x * c1.x + c1.y * c1.y);
    r2[d] = z * (c0.y * c1.x - c0.x * c1.y);
    __syncthreads();
    for (int off = QDIM / 2; off; off >>= 1) {
        if (d < off) { r0[d] += r0[d + off]; r1[d] += r1[d + off]; r2[d] += r2[d + off]; }
        __syncthreads();
    }
    float S00 = r0[0], S11 = r1[0], S01 = r2[0];
    __syncthreads();

    r0[d] = W[512 + d] + W[512 + QDIM + d];
    __syncthreads();
    for (int off = QDIM / 2; off; off >>= 1) {
        if (d < off) r0[d] += r0[d + off];
        __syncthreads();
    }
    if (d == 0) {
        float alpha = 0.5f * (S00 + S11);
        float beta  = 0.5f * (S00 - S11);
        float gamma = -S01;
        float R   = sqrtf(beta * beta + gamma * gamma);
        float phi = atan2f(gamma, beta);
        g_par[g][0] = r0[0];          // wsum
        g_par[g][1] = bv[0] - phi;    // theta offset (added in scan)
        g_par[g][2] = 0.5f * alpha;
        g_par[g][3] = 0.5f * R;
        g_par[g][4] = alpha;
        g_par[g][5] = R;
    }
}

// ---------------- prep: circuit (blocks 0-3) + xdot, 2 rows per warp (R8-proven) ----------------
__global__ void __launch_bounds__(256, 4) prep_kernel(
    const float* __restrict__ X,
    const float* __restrict__ Wf, const float* __restrict__ Wi,
    const float* __restrict__ Wg, const float* __restrict__ Wo,
    const float* __restrict__ bfv, const float* __restrict__ biv,
    const float* __restrict__ bgv, const float* __restrict__ bov,
    const float* __restrict__ Pf, const float* __restrict__ Pi,
    const float* __restrict__ Pg, const float* __restrict__ Po)
{
    if (blockIdx.x < 4) {
        int g = blockIdx.x;
        const float* P  = (g == 0) ? Pf : (g == 1) ? Pi : (g == 2) ? Pg : Po;
        const float* W  = (g == 0) ? Wf : (g == 1) ? Wi : (g == 2) ? Wg : Wo;
        const float* bv = (g == 0) ? bfv : (g == 1) ? biv : (g == 2) ? bgv : bov;
        circuit_block(g, P, W, bv);
        return;
    }

    int j    = blockIdx.x - 4;           // 0..2047 ; 16 rows per block
    int warp = threadIdx.x >> 5;
    int lane = threadIdx.x & 31;
    int rA   = j * 16 + warp * 2;        // rows rA, rA+1

    const float4* xa = (const float4*)(X + (size_t)rA * DIM_IN);
    const float4* xb = xa + (DIM_IN / 4);

    // front-batch all 8 X loads (MLP=8)
    float4 A0 = xa[lane], A1 = xa[lane + 32], A2 = xa[lane + 64], A3 = xa[lane + 96];
    float4 B0 = xb[lane], B1 = xb[lane + 32], B2 = xb[lane + 64], B3 = xb[lane + 96];

    float fA, fB, iA, iB, gA, gB, oA, oB;

#define GDOT(Wp, dA, dB)                                                          \
    {                                                                             \
        const float4* w4 = (const float4*)(Wp);                                   \
        float4 w0 = __ldg(w4 + lane),      w1 = __ldg(w4 + lane + 32),            \
               w2 = __ldg(w4 + lane + 64), w3 = __ldg(w4 + lane + 96);            \
        dA = dot4(w0, A0) + dot4(w1, A1) + dot4(w2, A2) + dot4(w3, A3);           \
        dB = dot4(w0, B0) + dot4(w1, B1) + dot4(w2, B2) + dot4(w3, B3);           \
    }
    GDOT(Wf, fA, fB)
    GDOT(Wi, iA, iB)
    GDOT(Wg, gA, gB)
    GDOT(Wo, oA, oB)
#undef GDOT

#pragma unroll
    for (int o = 16; o; o >>= 1) {
        fA += __shfl_xor_sync(0xffffffffu, fA, o);
        fB += __shfl_xor_sync(0xffffffffu, fB, o);
        iA += __shfl_xor_sync(0xffffffffu, iA, o);
        iB += __shfl_xor_sync(0xffffffffu, iB, o);
        gA += __shfl_xor_sync(0xffffffffu, gA, o);
        gB += __shfl_xor_sync(0xffffffffu, gB, o);
        oA += __shfl_xor_sync(0xffffffffu, oA, o);
        oB += __shfl_xor_sync(0xffffffffu, oB, o);
    }
    if (lane == 0) {
        g_xdot[rA]     = make_float4(fA, iA, gA, oA);
        g_xdot[rA + 1] = make_float4(fB, iB, gB, oB);
    }
}

// ---------------- scanout: fused scan + output write, 2 packed chains per block ----------------
// 64 blocks. Thread 0 runs TWO scalar recurrences packed in f32x2 registers
// (one FFMA2 issue slot drives both chains); MUFU ops run per-half.
// CONVERGENT loop (R10-proven): compute chunk k and write chunk k-1 in the
// same iteration; __syncthreads() at a single program point for all threads.
struct Qs { ull f, i, g, o; };

__global__ void __launch_bounds__(256) scanout_kernel(float4* __restrict__ out)
{
    const unsigned OUT4 = (unsigned)T_STEPS * BATCH * (HID / 4); // 4,194,304
    const unsigned HB4  = (unsigned)BATCH * (HID / 4);           // 16,384

    int b0  = blockIdx.x * 2;    // chains b0, b0+1
    int tid = threadIdx.x;

    __shared__ float2 sH[2][8];  // per chunk slot: H for both chains
    __shared__ float2 sHx, sCx;  // final h, c (both chains)

    // ---- chain state (only thread 0 uses it; others carry dead values) ----
    ull ws_f = bc2(g_par[0][0]), A2_f = bc2(g_par[0][2]), R2_f = bc2(g_par[0][3]);
    ull ws_i = bc2(g_par[1][0]), A2_i = bc2(g_par[1][2]), R2_i = bc2(g_par[1][3]);
    ull ws_g = bc2(g_par[2][0]), A_g  = bc2(g_par[2][4]), R_g  = bc2(g_par[2][5]);
    ull ws_o = bc2(g_par[3][0]), A2_o = bc2(g_par[3][2]), R2_o = bc2(g_par[3][3]);
    ull off_f = bc2(g_par[0][1]), off_i = bc2(g_par[1][1]);
    ull off_g = bc2(g_par[2][1]), off_o = bc2(g_par[3][1]);

    const ull K3 = bc2(-17.f / 315.f), K2 = bc2(2.f / 15.f);
    const ull K1 = bc2(-1.f / 3.f), ONE2 = bc2(1.f), HALF2 = bc2(0.5f);

    ull H2 = 0, C2 = 0;   // packed (0.0f, 0.0f)
    const float4* Xd = g_xdot;

#define LOADADJ(t, s)                                                  \
    {                                                                  \
        float4 a_ = Xd[(t) * BATCH + b0];                              \
        float4 b_ = Xd[(t) * BATCH + b0 + 1];                          \
        (s).f = add2(pk(a_.x, b_.x), off_f);                           \
        (s).i = add2(pk(a_.y, b_.y), off_i);                           \
        (s).g = add2(pk(a_.z, b_.z), off_g);                           \
        (s).o = add2(pk(a_.w, b_.w), off_o);                           \
    }

#define SIG2(uu, res)                                                  \
    {                                                                  \
        ull s_ = mul2(uu, uu);                                         \
        ull p_ = fma2(s_, K3, K2);                                     \
        p_ = fma2(s_, p_, K1);                                         \
        p_ = fma2(s_, p_, ONE2);                                       \
        p_ = mul2(uu, p_);                                             \
        res = fma2(p_, HALF2, HALF2);                                  \
    }

#define STEP(xd, kk, jj)                                               \
    {                                                                  \
        ull thf = fma2(H2, ws_f, (xd).f);                              \
        ull thi = fma2(H2, ws_i, (xd).i);                              \
        ull thg = fma2(H2, ws_g, (xd).g);                              \
        ull tho = fma2(H2, ws_o, (xd).o);                              \
        ull cf = cos2p(thf), ci = cos2p(thi);                          \
        ull cg = cos2p(thg), co = cos2p(tho);                          \
        ull uf = fma2(R2_f, cf, A2_f); ull fv; SIG2(uf, fv);           \
        ull ui = fma2(R2_i, ci, A2_i); ull iv; SIG2(ui, iv);           \
        ull ug = fma2(R_g, cg, A_g);   ull gv = tanh2p(ug);            \
        ull uo = fma2(R2_o, co, A2_o); ull ov; SIG2(uo, ov);           \
        C2 = fma2(fv, C2, mul2(iv, gv));                               \
        ull tC = tanh2p(C2);                                           \
        H2 = mul2(ov, tC);                                             \
        sH[(kk) & 1][jj] = upk(H2);                                    \
    }

    Qs q[8];
    if (tid == 0) {
#pragma unroll
        for (int j = 0; j < 8; j++) LOADADJ(j, q[j]);
    }

    // 32 compute chunks + 1 drain; writers trail compute by one chunk.
    // Barrier is OUTSIDE all role conditionals — single convergent point.
#pragma unroll 1
    for (int k = 0; k <= CHUNKS; k++) {
        if (tid == 0) {
            if (k < CHUNKS) {
                int t0 = k * 8;
#pragma unroll
                for (int j = 0; j < 8; j++) {
                    Qs cur = q[j];
                    if (t0 + 8 + j < T_STEPS) LOADADJ(t0 + 8 + j, q[j]);
                    STEP(cur, k, j);
                }
            } else {
                sHx = sH[(CHUNKS - 1) & 1][7];
                sCx = upk(C2);
            }
        }
        if (tid >= 32 && k >= 1) {
            int c = k - 1;                        // chunk being written
            const float2* hs = sH[c & 1];
            unsigned rowbase = (unsigned)c * 8u;
            int wtid = tid - 32;                  // 0..223
#pragma unroll 1
            for (int u = wtid; u < 2048; u += 224) {
                int tl    = u >> 8;               // 0..7
                int chain = (u >> 7) & 1;
                int pos   = u & 127;
                float2 hv = hs[tl];
                float v = chain ? hv.y : hv.x;
                unsigned idx = ((rowbase + tl) * BATCH + (unsigned)(b0 + chain)) * (HID / 4) + pos;
                __stcs(out + idx, make_float4(v, v, v, v));
            }
        }
        __syncthreads();
    }
#undef STEP
#undef SIG2
#undef LOADADJ

    // tail: finals visible after the loop's last barrier; all threads write.
    {
        float2 hfin = sHx, cfin = sCx;
        int chain = (tid >> 7) & 1;     // 256 threads: 2 chains x 128 positions
        int pos   = tid & 127;
        float hv = chain ? hfin.y : hfin.x;
        float cv = chain ? cfin.y : cfin.x;
        unsigned base = (unsigned)(b0 + chain) * (HID / 4) + pos;
        __stcs(out + OUT4 + base, make_float4(hv, hv, hv, hv));
        __stcs(out + OUT4 + HB4 + base, make_float4(cv, cv, cv, cv));
    }
}

// ---------------- launch ----------------
extern "C" void kernel_launch(void* const* d_in, const int* in_sizes, int n_in,
                              void* d_out, int out_size)
{
    const float* X  = (const float*)d_in[0];
    const float* Wf = (const float*)d_in[1];
    const float* bf = (const float*)d_in[2];
    const float* Pf = (const float*)d_in[3];
    const float* Wi = (const float*)d_in[4];
    const float* bi = (const float*)d_in[5];
    const float* Pi = (const float*)d_in[6];
    const float* Wg = (const float*)d_in[7];
    const float* bg = (const float*)d_in[8];
    const float* Pg = (const float*)d_in[9];
    const float* Wo = (const float*)d_in[10];
    const float* bo = (const float*)d_in[11];
    const float* Po = (const float*)d_in[12];

    // blocks 0-3: circuits; blocks 4..2051: xdot (32768 rows / 16 rows per block)
    prep_kernel<<<4 + (T_STEPS * BATCH) / 16, 256>>>(
        X, Wf, Wi, Wg, Wo, bf, bi, bg, bo, Pf, Pi, Pg, Po);

    // 64 blocks x 2 packed chains; scan + output streaming fused
    scanout_kernel<<<BATCH / 2, 256>>>((float4*)d_out);
}

// round 15
// speedup vs baseline: 1.3005x; 1.0250x over previous
#include <cuda_runtime.h>
#include <cuda_bf16.h>

#define T_STEPS 256
#define BATCH   128
#define DIM_IN  512
#define HID     512
#define NQ      8
#define QDIM    256   // 2^8
#define CHUNK   16    // timesteps per chunk
#define NCHUNK  (T_STEPS / CHUNK)   // 16

// ---------------- scratch (no allocations allowed) ----------------
__device__ float4 g_xdot[T_STEPS * BATCH];   // per (t,b): raw dots for f,i,g,o
// per gate: [0]=wsum  [1]=b0-phi  [2]=alpha/2  [3]=R/2  [4]=alpha  [5]=R
__device__ float  g_par[4][6];

__device__ __forceinline__ float2 cmul(float2 a, float2 b) {
    return make_float2(a.x * b.x - a.y * b.y, a.x * b.y + a.y * b.x);
}
__device__ __forceinline__ float2 cadd(float2 a, float2 b) {
    return make_float2(a.x + b.x, a.y + b.y);
}
__device__ __forceinline__ float htanh(float x) {
    float y;
    asm("tanh.approx.f32 %0, %1;" : "=f"(y) : "f"(x));
    return y;
}
__device__ __forceinline__ float dot4(float4 w, float4 x) {
    return w.x * x.x + w.y * x.y + w.z * x.z + w.w * x.w;
}

// ---------------- circuit: simulate one variational circuit ----------------
// Statevector-simulates columns 0 and 128 of the 2-layer circuit, reduces to
// expval(theta) = alpha + R*cos(theta - phi), plus wsum and b0-phi.
__device__ void circuit_block(int g, const float* __restrict__ P,
                              const float* __restrict__ W, const float* __restrict__ bv)
{
    __shared__ float2 a0[QDIM], a1[QDIM];
    __shared__ float  r0[QDIM], r1[QDIM], r2[QDIM];
    int d = threadIdx.x;

    a0[d] = make_float2(d == 0 ? 1.f : 0.f, 0.f);
    a1[d] = make_float2(d == QDIM / 2 ? 1.f : 0.f, 0.f);

    for (int l = 0; l < 2; l++) {
        for (int w = 0; w < NQ; w++) {
            const float* p = P + (l * NQ + w) * 3;
            float phi = p[0], th = p[1], om = p[2];
            float c, s;  __sincosf(0.5f * th, &s, &c);
            float cap, sap; __sincosf(0.5f * (phi + om), &sap, &cap);
            float cbm, sbm; __sincosf(0.5f * (phi - om), &sbm, &cbm);
            float2 m00 = make_float2(cap * c, -sap * c);     // ep*c
            float2 m01 = make_float2(-cbm * s, -sbm * s);    // -em*s
            float2 m10 = make_float2(cbm * s, -sbm * s);     // conj(em)*s
            float2 m11 = make_float2(cap * c, sap * c);      // conj(ep)*c

            int p7 = 7 - w;
            int mask = 1 << p7;
            int bit = (d >> p7) & 1;
            __syncthreads();
            float2 me0 = a0[d], pa0 = a0[d ^ mask];
            float2 me1 = a1[d], pa1 = a1[d ^ mask];
            __syncthreads();
            float2 n0, n1;
            if (!bit) {
                n0 = cadd(cmul(m00, me0), cmul(m01, pa0));
                n1 = cadd(cmul(m00, me1), cmul(m01, pa1));
            } else {
                n0 = cadd(cmul(m10, pa0), cmul(m11, me0));
                n1 = cadd(cmul(m10, pa1), cmul(m11, me1));
            }
            a0[d] = n0; a1[d] = n1;
        }
        for (int w = 0; w < NQ - 1; w++) {
            int pc = 7 - w, pt = 6 - w;
            __syncthreads();
            int src = ((d >> pc) & 1) ? (d ^ (1 << pt)) : d;
            float2 v0 = a0[src], v1 = a1[src];
            __syncthreads();
            a0[d] = v0; a1[d] = v1;
        }
    }
    __syncthreads();

    float z = (d < QDIM / 2) ? 1.f : -1.f;
    float2 c0 = a0[d], c1 = a1[d];
    r0[d] = z * (c0.x * c0.x + c0.y * c0.y);
    r1[d] = z * (c1.x * c1.x + c1.y * c1.y);
    r2[d] = z * (c0.y * c1.x - c0.x * c1.y);
    __syncthreads();
    for (int off = QDIM / 2; off; off >>= 1) {
        if (d < off) { r0[d] += r0[d + off]; r1[d] += r1[d + off]; r2[d] += r2[d + off]; }
        __syncthreads();
    }
    float S00 = r0[0], S11 = r1[0], S01 = r2[0];
    __syncthreads();

    r0[d] = W[512 + d] + W[512 + QDIM + d];
    __syncthreads();
    for (int off = QDIM / 2; off; off >>= 1) {
        if (d < off) r0[d] += r0[d + off];
        __syncthreads();
    }
    if (d == 0) {
        float alpha = 0.5f * (S00 + S11);
        float beta  = 0.5f * (S00 - S11);
        float gamma = -S01;
        float R   = sqrtf(beta * beta + gamma * gamma);
        float phi = atan2f(gamma, beta);
        g_par[g][0] = r0[0];          // wsum
        g_par[g][1] = bv[0] - phi;    // theta offset (added in scan)
        g_par[g][2] = 0.5f * alpha;
        g_par[g][3] = 0.5f * R;
        g_par[g][4] = alpha;
        g_par[g][5] = R;
    }
}

// ---------------- prep: circuit (blocks 0-3) + xdot, 2 rows per warp (R8-proven) ----------------
// X streamed once -> __ldcs (evict-first) keeps L1 for the weight working set.
__global__ void __launch_bounds__(256, 4) prep_kernel(
    const float* __restrict__ X,
    const float* __restrict__ Wf, const float* __restrict__ Wi,
    const float* __restrict__ Wg, const float* __restrict__ Wo,
    const float* __restrict__ bfv, const float* __restrict__ biv,
    const float* __restrict__ bgv, const float* __restrict__ bov,
    const float* __restrict__ Pf, const float* __restrict__ Pi,
    const float* __restrict__ Pg, const float* __restrict__ Po)
{
    if (blockIdx.x < 4) {
        int g = blockIdx.x;
        const float* P  = (g == 0) ? Pf : (g == 1) ? Pi : (g == 2) ? Pg : Po;
        const float* W  = (g == 0) ? Wf : (g == 1) ? Wi : (g == 2) ? Wg : Wo;
        const float* bv = (g == 0) ? bfv : (g == 1) ? biv : (g == 2) ? bgv : bov;
        circuit_block(g, P, W, bv);
        return;
    }

    int j    = blockIdx.x - 4;           // 0..2047 ; 16 rows per block
    int warp = threadIdx.x >> 5;
    int lane = threadIdx.x & 31;
    int rA   = j * 16 + warp * 2;        // rows rA, rA+1

    const float4* xa = (const float4*)(X + (size_t)rA * DIM_IN);
    const float4* xb = xa + (DIM_IN / 4);

    // front-batch all 8 X loads (MLP=8), streaming (evict-first)
    float4 A0 = __ldcs(xa + lane), A1 = __ldcs(xa + lane + 32),
           A2 = __ldcs(xa + lane + 64), A3 = __ldcs(xa + lane + 96);
    float4 B0 = __ldcs(xb + lane), B1 = __ldcs(xb + lane + 32),
           B2 = __ldcs(xb + lane + 64), B3 = __ldcs(xb + lane + 96);

    float fA, fB, iA, iB, gA, gB, oA, oB;

#define GDOT(Wp, dA, dB)                                                          \
    {                                                                             \
        const float4* w4 = (const float4*)(Wp);                                   \
        float4 w0 = __ldg(w4 + lane),      w1 = __ldg(w4 + lane + 32),            \
               w2 = __ldg(w4 + lane + 64), w3 = __ldg(w4 + lane + 96);            \
        dA = dot4(w0, A0) + dot4(w1, A1) + dot4(w2, A2) + dot4(w3, A3);           \
        dB = dot4(w0, B0) + dot4(w1, B1) + dot4(w2, B2) + dot4(w3, B3);           \
    }
    GDOT(Wf, fA, fB)
    GDOT(Wi, iA, iB)
    GDOT(Wg, gA, gB)
    GDOT(Wo, oA, oB)
#undef GDOT

#pragma unroll
    for (int o = 16; o; o >>= 1) {
        fA += __shfl_xor_sync(0xffffffffu, fA, o);
        fB += __shfl_xor_sync(0xffffffffu, fB, o);
        iA += __shfl_xor_sync(0xffffffffu, iA, o);
        iB += __shfl_xor_sync(0xffffffffu, iB, o);
        gA += __shfl_xor_sync(0xffffffffu, gA, o);
        gB += __shfl_xor_sync(0xffffffffu, gB, o);
        oA += __shfl_xor_sync(0xffffffffu, oA, o);
        oB += __shfl_xor_sync(0xffffffffu, oB, o);
    }
    if (lane == 0) {
        g_xdot[rA]     = make_float4(fA, iA, gA, oA);
        g_xdot[rA + 1] = make_float4(fB, iB, gB, oB);
    }
}

// ---------------- scanout: fused scan + output write (R10-proven, CHUNK=16) ----------------
// One block per batch element. Thread 0 runs the scalar recurrence; each
// 16-step chunk is staged into double-buffered smem, and threads 32..255
// stream the previous chunk's 512-wide output rows to d_out concurrently.
// Convergent barrier: single __syncthreads() per iteration, outside all roles.
__device__ __forceinline__ float ptanh_half(float x) {   // |x| <= ~0.55
    float t = x * x;
    float p = fmaf(t, -17.f / 315.f, 2.f / 15.f);
    p = fmaf(t, p, -1.f / 3.f);
    p = fmaf(t, p, 1.f);
    return x * p;
}

__global__ void __launch_bounds__(256) scanout_kernel(float4* __restrict__ out)
{
    const unsigned OUT4 = (unsigned)T_STEPS * BATCH * (HID / 4); // 4,194,304
    const unsigned HB4  = (unsigned)BATCH * (HID / 4);           // 16,384

    int b   = blockIdx.x;        // batch element
    int tid = threadIdx.x;

    __shared__ float sH[2][CHUNK];
    __shared__ float sC;

    // chain-local parameters (only thread 0 really uses them)
    float ws_f = g_par[0][0], A2_f = g_par[0][2], R2_f = g_par[0][3];
    float ws_i = g_par[1][0], A2_i = g_par[1][2], R2_i = g_par[1][3];
    float ws_g = g_par[2][0], A_g  = g_par[2][4], R_g  = g_par[2][5];
    float ws_o = g_par[3][0], A2_o = g_par[3][2], R2_o = g_par[3][3];
    float off_f = g_par[0][1], off_i = g_par[1][1], off_g = g_par[2][1], off_o = g_par[3][1];

    float H = 0.f, C = 0.f;
    const float4* Xd = g_xdot;

#define LOADADJ(t) \
    ({ float4 v_ = Xd[(t) * BATCH + b]; \
       v_.x += off_f; v_.y += off_i; v_.z += off_g; v_.w += off_o; v_; })

    float4 q[8];
    if (tid == 0) {
#pragma unroll
        for (int j = 0; j < 8; j++) q[j] = LOADADJ(j);
    }

#define STEP(xd, kk, jj)                                              \
    {                                                                 \
        float cf = __cosf(fmaf(H, ws_f, (xd).x));                     \
        float ci = __cosf(fmaf(H, ws_i, (xd).y));                     \
        float cg = __cosf(fmaf(H, ws_g, (xd).z));                     \
        float co = __cosf(fmaf(H, ws_o, (xd).w));                     \
        float fv = fmaf(ptanh_half(fmaf(R2_f, cf, A2_f)), 0.5f, 0.5f);\
        float iv = fmaf(ptanh_half(fmaf(R2_i, ci, A2_i)), 0.5f, 0.5f);\
        float gv = htanh(fmaf(R_g, cg, A_g));                         \
        float ov = fmaf(ptanh_half(fmaf(R2_o, co, A2_o)), 0.5f, 0.5f);\
        C = fmaf(fv, C, iv * gv);                                     \
        H = ov * htanh(C);                                            \
        sH[(kk) & 1][jj] = H;                                         \
    }

    // NCHUNK compute chunks + 1 drain; writers trail compute by one chunk.
#pragma unroll 1
    for (int k = 0; k <= NCHUNK; k++) {
        if (tid == 0) {
            if (k < NCHUNK) {
                int t0 = k * CHUNK;
#pragma unroll
                for (int j = 0; j < CHUNK; j++) {
                    float4 cur = q[j & 7];
                    if (t0 + j + 8 < T_STEPS) q[j & 7] = LOADADJ(t0 + j + 8);
                    STEP(cur, k, j);
                }
            } else {
                sC = C;
            }
        }
        if (tid >= 32 && k >= 1) {
            int c = k - 1;                        // chunk being written
            const float* hs = sH[c & 1];
            unsigned rowbase = (unsigned)c * CHUNK;
            int wtid = tid - 32;                  // 0..223
#pragma unroll 1
            for (int u = wtid; u < CHUNK * 128; u += 224) {
                int tl  = u >> 7;                 // 0..CHUNK-1
                int pos = u & 127;                // float4 within 512-wide row
                float v = hs[tl];
                unsigned idx = ((rowbase + tl) * BATCH + (unsigned)b) * (HID / 4) + pos;
                __stcs(out + idx, make_float4(v, v, v, v));
            }
        }
        __syncthreads();
    }
#undef STEP
#undef LOADADJ

    // tail: hx (= H at t=255, in sH[(NCHUNK-1)&1][CHUNK-1]) and cx (= sC)
    float hfin = sH[(NCHUNK - 1) & 1][CHUNK - 1];
    float cfin = sC;
    if (tid < 128) {
        unsigned idx = OUT4 + (unsigned)b * (HID / 4) + tid;
        __stcs(out + idx, make_float4(hfin, hfin, hfin, hfin));
    } else {
        unsigned idx = OUT4 + HB4 + (unsigned)b * (HID / 4) + (tid - 128);
        __stcs(out + idx, make_float4(cfin, cfin, cfin, cfin));
    }
}

// ---------------- launch ----------------
extern "C" void kernel_launch(void* const* d_in, const int* in_sizes, int n_in,
                              void* d_out, int out_size)
{
    const float* X  = (const float*)d_in[0];
    const float* Wf = (const float*)d_in[1];
    const float* bf = (const float*)d_in[2];
    const float* Pf = (const float*)d_in[3];
    const float* Wi = (const float*)d_in[4];
    const float* bi = (const float*)d_in[5];
    const float* Pi = (const float*)d_in[6];
    const float* Wg = (const float*)d_in[7];
    const float* bg = (const float*)d_in[8];
    const float* Pg = (const float*)d_in[9];
    const float* Wo = (const float*)d_in[10];
    const float* bo = (const float*)d_in[11];
    const float* Po = (const float*)d_in[12];

    // blocks 0-3: circuits; blocks 4..2051: xdot (32768 rows / 16 rows per block)
    prep_kernel<<<4 + (T_STEPS * BATCH) / 16, 256>>>(
        X, Wf, Wi, Wg, Wo, bf, bi, bg, bo, Pf, Pi, Pg, Po);

    // one block per batch element; scan + output streaming fused
    scanout_kernel<<<BATCH, 256>>>((float4*)d_out);
}

// round 16
// speedup vs baseline: 1.7306x; 1.3307x over previous
#include <cuda_runtime.h>
#include <cuda_bf16.h>

#define T_STEPS 256
#define BATCH   128
#define DIM_IN  512
#define HID     512
#define NQ      8
#define QDIM    256   // 2^8

// ---------------- scratch (no allocations allowed) ----------------
__device__ float4 g_xdot[T_STEPS * BATCH];   // per (t,b): raw dots for f,i,g,o
// per gate: [0]=wsum  [1]=b0-phi  [2]=alpha/2  [3]=R/2  [4]=alpha  [5]=R
__device__ float  g_par[4][6];

__device__ __forceinline__ float2 cmul(float2 a, float2 b) {
    return make_float2(a.x * b.x - a.y * b.y, a.x * b.y + a.y * b.x);
}
__device__ __forceinline__ float2 cadd(float2 a, float2 b) {
    return make_float2(a.x + b.x, a.y + b.y);
}
__device__ __forceinline__ float htanh(float x) {
    float y;
    asm("tanh.approx.f32 %0, %1;" : "=f"(y) : "f"(x));
    return y;
}
__device__ __forceinline__ float dot4(float4 w, float4 x) {
    return w.x * x.x + w.y * x.y + w.z * x.z + w.w * x.w;
}

// ---------------- circuit: simulate one variational circuit ----------------
// Statevector-simulates columns 0 and 128 of the 2-layer circuit, reduces to
// expval(theta) = alpha + R*cos(theta - phi), plus wsum and b0-phi.
__device__ void circuit_block(int g, const float* __restrict__ P,
                              const float* __restrict__ W, const float* __restrict__ bv)
{
    __shared__ float2 a0[QDIM], a1[QDIM];
    __shared__ float  r0[QDIM], r1[QDIM], r2[QDIM];
    int d = threadIdx.x;

    a0[d] = make_float2(d == 0 ? 1.f : 0.f, 0.f);
    a1[d] = make_float2(d == QDIM / 2 ? 1.f : 0.f, 0.f);

    for (int l = 0; l < 2; l++) {
        for (int w = 0; w < NQ; w++) {
            const float* p = P + (l * NQ + w) * 3;
            float phi = p[0], th = p[1], om = p[2];
            float c, s;  __sincosf(0.5f * th, &s, &c);
            float cap, sap; __sincosf(0.5f * (phi + om), &sap, &cap);
            float cbm, sbm; __sincosf(0.5f * (phi - om), &sbm, &cbm);
            float2 m00 = make_float2(cap * c, -sap * c);     // ep*c
            float2 m01 = make_float2(-cbm * s, -sbm * s);    // -em*s
            float2 m10 = make_float2(cbm * s, -sbm * s);     // conj(em)*s
            float2 m11 = make_float2(cap * c, sap * c);      // conj(ep)*c

            int p7 = 7 - w;
            int mask = 1 << p7;
            int bit = (d >> p7) & 1;
            __syncthreads();
            float2 me0 = a0[d], pa0 = a0[d ^ mask];
            float2 me1 = a1[d], pa1 = a1[d ^ mask];
            __syncthreads();
            float2 n0, n1;
            if (!bit) {
                n0 = cadd(cmul(m00, me0), cmul(m01, pa0));
                n1 = cadd(cmul(m00, me1), cmul(m01, pa1));
            } else {
                n0 = cadd(cmul(m10, pa0), cmul(m11, me0));
                n1 = cadd(cmul(m10, pa1), cmul(m11, me1));
            }
            a0[d] = n0; a1[d] = n1;
        }
        for (int w = 0; w < NQ - 1; w++) {
            int pc = 7 - w, pt = 6 - w;
            __syncthreads();
            int src = ((d >> pc) & 1) ? (d ^ (1 << pt)) : d;
            float2 v0 = a0[src], v1 = a1[src];
            __syncthreads();
            a0[d] = v0; a1[d] = v1;
        }
    }
    __syncthreads();

    float z = (d < QDIM / 2) ? 1.f : -1.f;
    float2 c0 = a0[d], c1 = a1[d];
    r0[d] = z * (c0.x * c0.x + c0.y * c0.y);
    r1[d] = z * (c1.x * c1.x + c1.y * c1.y);
    r2[d] = z * (c0.y * c1.x - c0.x * c1.y);
    __syncthreads();
    for (int off = QDIM / 2; off; off >>= 1) {
        if (d < off) { r0[d] += r0[d + off]; r1[d] += r1[d + off]; r2[d] += r2[d + off]; }
        __syncthreads();
    }
    float S00 = r0[0], S11 = r1[0], S01 = r2[0];
    __syncthreads();

    r0[d] = W[512 + d] + W[512 + QDIM + d];
    __syncthreads();
    for (int off = QDIM / 2; off; off >>= 1) {
        if (d < off) r0[d] += r0[d + off];
        __syncthreads();
    }
    if (d == 0) {
        float alpha = 0.5f * (S00 + S11);
        float beta  = 0.5f * (S00 - S11);
        float gamma = -S01;
        float R   = sqrtf(beta * beta + gamma * gamma);
        float phi = atan2f(gamma, beta);
        g_par[g][0] = r0[0];          // wsum
        g_par[g][1] = bv[0] - phi;    // theta offset (added in scan)
        g_par[g][2] = 0.5f * alpha;
        g_par[g][3] = 0.5f * R;
        g_par[g][4] = alpha;
        g_par[g][5] = R;
    }
}

// ---------------- prep: circuit (blocks 0-3) + xdot, 2 rows per warp (R8 form) ----------------
__global__ void __launch_bounds__(256, 4) prep_kernel(
    const float* __restrict__ X,
    const float* __restrict__ Wf, const float* __restrict__ Wi,
    const float* __restrict__ Wg, const float* __restrict__ Wo,
    const float* __restrict__ bfv, const float* __restrict__ biv,
    const float* __restrict__ bgv, const float* __restrict__ bov,
    const float* __restrict__ Pf, const float* __restrict__ Pi,
    const float* __restrict__ Pg, const float* __restrict__ Po)
{
    if (blockIdx.x < 4) {
        int g = blockIdx.x;
        const float* P  = (g == 0) ? Pf : (g == 1) ? Pi : (g == 2) ? Pg : Po;
        const float* W  = (g == 0) ? Wf : (g == 1) ? Wi : (g == 2) ? Wg : Wo;
        const float* bv = (g == 0) ? bfv : (g == 1) ? biv : (g == 2) ? bgv : bov;
        circuit_block(g, P, W, bv);
        return;
    }

    int j    = blockIdx.x - 4;           // 0..2047 ; 16 rows per block
    int warp = threadIdx.x >> 5;
    int lane = threadIdx.x & 31;
    int rA   = j * 16 + warp * 2;        // rows rA, rA+1

    const float4* xa = (const float4*)(X + (size_t)rA * DIM_IN);
    const float4* xb = xa + (DIM_IN / 4);

    // front-batch all 8 X loads (MLP=8)
    float4 A0 = xa[lane], A1 = xa[lane + 32], A2 = xa[lane + 64], A3 = xa[lane + 96];
    float4 B0 = xb[lane], B1 = xb[lane + 32], B2 = xb[lane + 64], B3 = xb[lane + 96];

    float fA, fB, iA, iB, gA, gB, oA, oB;

#define GDOT(Wp, dA, dB)                                                          \
    {                                                                             \
        const float4* w4 = (const float4*)(Wp);                                   \
        float4 w0 = __ldg(w4 + lane),      w1 = __ldg(w4 + lane + 32),            \
               w2 = __ldg(w4 + lane + 64), w3 = __ldg(w4 + lane + 96);            \
        dA = dot4(w0, A0) + dot4(w1, A1) + dot4(w2, A2) + dot4(w3, A3);           \
        dB = dot4(w0, B0) + dot4(w1, B1) + dot4(w2, B2) + dot4(w3, B3);           \
    }
    GDOT(Wf, fA, fB)
    GDOT(Wi, iA, iB)
    GDOT(Wg, gA, gB)
    GDOT(Wo, oA, oB)
#undef GDOT

#pragma unroll
    for (int o = 16; o; o >>= 1) {
        fA += __shfl_xor_sync(0xffffffffu, fA, o);
        fB += __shfl_xor_sync(0xffffffffu, fB, o);
        iA += __shfl_xor_sync(0xffffffffu, iA, o);
        iB += __shfl_xor_sync(0xffffffffu, iB, o);
        gA += __shfl_xor_sync(0xffffffffu, gA, o);
        gB += __shfl_xor_sync(0xffffffffu, gB, o);
        oA += __shfl_xor_sync(0xffffffffu, oA, o);
        oB += __shfl_xor_sync(0xffffffffu, oB, o);
    }
    if (lane == 0) {
        g_xdot[rA]     = make_float4(fA, iA, gA, oA);
        g_xdot[rA + 1] = make_float4(fB, iB, gB, oB);
    }
}

// ---------------- scanout: fused scan + output write ----------------
// One block per batch element. Thread 0 runs the scalar recurrence; every
// 8-step chunk it stages H into double-buffered smem, and threads 32..255
// stream the previous chunk's 512-wide output rows to d_out concurrently.
// Only block-local __syncthreads — no cross-block sync.
__device__ __forceinline__ float ptanh_half(float x) {   // |x| <= ~0.55
    float t = x * x;
    float p = fmaf(t, -17.f / 315.f, 2.f / 15.f);
    p = fmaf(t, p, -1.f / 3.f);
    p = fmaf(t, p, 1.f);
    return x * p;
}

__global__ void __launch_bounds__(256) scanout_kernel(float4* __restrict__ out)
{
    const unsigned OUT4 = (unsigned)T_STEPS * BATCH * (HID / 4); // 4,194,304
    const unsigned HB4  = (unsigned)BATCH * (HID / 4);           // 16,384

    int b   = blockIdx.x;        // batch element
    int tid = threadIdx.x;

    __shared__ float sH[2][8];
    __shared__ float sC;

    // chain-local parameters (only thread 0 really uses them)
    float ws_f = g_par[0][0], A2_f = g_par[0][2], R2_f = g_par[0][3];
    float ws_i = g_par[1][0], A2_i = g_par[1][2], R2_i = g_par[1][3];
    float ws_g = g_par[2][0], A_g  = g_par[2][4], R_g  = g_par[2][5];
    float ws_o = g_par[3][0], A2_o = g_par[3][2], R2_o = g_par[3][3];
    float off_f = g_par[0][1], off_i = g_par[1][1], off_g = g_par[2][1], off_o = g_par[3][1];

    float H = 0.f, C = 0.f;
    const float4* Xd = g_xdot;

#define LOADADJ(t) \
    ({ float4 v_ = Xd[(t) * BATCH + b]; \
       v_.x += off_f; v_.y += off_i; v_.z += off_g; v_.w += off_o; v_; })

    float4 q[8];
    if (tid == 0) {
#pragma unroll
        for (int j = 0; j < 8; j++) q[j] = LOADADJ(j);
    }

#define STEP(xd, kk, jj)                                              \
    {                                                                 \
        float cf = __cosf(fmaf(H, ws_f, (xd).x));                     \
        float ci = __cosf(fmaf(H, ws_i, (xd).y));                     \
        float cg = __cosf(fmaf(H, ws_g, (xd).z));                     \
        float co = __cosf(fmaf(H, ws_o, (xd).w));                     \
        float fv = fmaf(ptanh_half(fmaf(R2_f, cf, A2_f)), 0.5f, 0.5f);\
        float iv = fmaf(ptanh_half(fmaf(R2_i, ci, A2_i)), 0.5f, 0.5f);\
        float gv = htanh(fmaf(R_g, cg, A_g));                         \
        float ov = fmaf(ptanh_half(fmaf(R2_o, co, A2_o)), 0.5f, 0.5f);\
        C = fmaf(fv, C, iv * gv);                                     \
        H = ov * htanh(C);                                            \
        sH[(kk) & 1][jj] = H;                                         \
    }

    // 32 compute chunks + 1 drain iteration; writers trail compute by one chunk
#pragma unroll 1
    for (int k = 0; k <= 32; k++) {
        if (tid == 0) {
            if (k < 32) {
                int t0 = k * 8;
#pragma unroll
                for (int j = 0; j < 8; j++) {
                    float4 cur = q[j];
                    if (t0 + 8 + j < T_STEPS) q[j] = LOADADJ(t0 + 8 + j);
                    STEP(cur, k, j);
                }
            } else {
                sC = C;
            }
        }
        if (tid >= 32 && k >= 1) {
            int c = k - 1;                       // chunk being written
            const float* hs = sH[c & 1];
            unsigned rowbase = (unsigned)c * 8u; // first t of chunk
#pragma unroll 1
            for (int u = tid - 32; u < 1024; u += 224) {
                int tl  = u >> 7;                // 0..7
                int pos = u & 127;               // float4 within the 512-wide row
                float v = hs[tl];
                unsigned idx = ((rowbase + tl) * BATCH + (unsigned)b) * (HID / 4) + pos;
                __stcs(out + idx, make_float4(v, v, v, v));
            }
        }
        __syncthreads();
    }
#undef STEP
#undef LOADADJ

    // tail: hx (= H at t=255, in sH[1][7]) and cx (= sC)
    float hfin = sH[1][7];
    float cfin = sC;
    if (tid < 128) {
        unsigned idx = OUT4 + (unsigned)b * (HID / 4) + tid;
        __stcs(out + idx, make_float4(hfin, hfin, hfin, hfin));
    } else {
        unsigned idx = OUT4 + HB4 + (unsigned)b * (HID / 4) + (tid - 128);
        __stcs(out + idx, make_float4(cfin, cfin, cfin, cfin));
    }
}

// ---------------- launch ----------------
extern "C" void kernel_launch(void* const* d_in, const int* in_sizes, int n_in,
                              void* d_out, int out_size)
{
    const float* X  = (const float*)d_in[0];
    const float* Wf = (const float*)d_in[1];
    const float* bf = (const float*)d_in[2];
    const float* Pf = (const float*)d_in[3];
    const float* Wi = (const float*)d_in[4];
    const float* bi = (const float*)d_in[5];
    const float* Pi = (const float*)d_in[6];
    const float* Wg = (const float*)d_in[7];
    const float* bg = (const float*)d_in[8];
    const float* Pg = (const float*)d_in[9];
    const float* Wo = (const float*)d_in[10];
    const float* bo = (const float*)d_in[11];
    const float* Po = (const float*)d_in[12];

    // blocks 0-3: circuits; blocks 4..2051: xdot (32768 rows / 16 rows per block)
    prep_kernel<<<4 + (T_STEPS * BATCH) / 16, 256>>>(
        X, Wf, Wi, Wg, Wo, bf, bi, bg, bo, Pf, Pi, Pg, Po);

    // one block per batch element; scan + output streaming fused
    scanout_kernel<<<BATCH, 256>>>((float4*)d_out);
}